// round 11
// baseline (speedup 1.0000x reference)
#include <cuda_runtime.h>

// ---------------------------------------------------------------------------
// ConfidenceAwareSSIM: B=16, C=3, H=W=512, fp32.
// loss = mean( clip(1 - SSIM(x,y), 0, 1) * conf ), 11x11 Gaussian, zero pad.
//
// R11 changes vs R9 (74.2us best; R10 persistent-CTA FAILED/reverted):
//  * Phase-1 units widened 4 -> 8 output columns: 14 LDG.128 per 8 outputs
//    instead of 10 per 4  ->  phase-1 L1 read bytes/pixel 40 -> 28 (-30%),
//    and half the unit-loop iterations (592 vs 1184).
//  * In-place squaring (vs[i] *= vs[i] after the S,D convs) keeps the live
//    set at ~56 floats so regs stay within the 85-reg / 3-CTA budget.
// ---------------------------------------------------------------------------

#define BATCH 16
#define CH    3
#define HH    512
#define WW    512

#define TW    64
#define TH    64
#define HALO  5
#define SH    (TH + 2*HALO)       // 74
#define NBLOCKS (8*8*48)

#define SMEM_FLOATS (4*SH*TW)     // two float2 planes: (S,D), (A,B)
#define SMEM_BYTES  (SMEM_FLOATS * 4)   // 75,776 B

// Gaussian taps (symmetric, normalized) as literals.
__device__ __forceinline__ constexpr float gw(int k) {
    const int d = (k <= 5) ? k : (10 - k);
    return (d == 0) ? 0.00102838f
         : (d == 1) ? 0.00759876f
         : (d == 2) ? 0.03600078f
         : (d == 3) ? 0.10936070f
         : (d == 4) ? 0.21300554f
         :            0.26601173f;
}

__device__ float    g_accum  = 0.0f;
__device__ unsigned g_ticket = 0u;

__global__ void __launch_bounds__(256, 3)
ssim_tile_kernel(const float* __restrict__ gx, const float* __restrict__ gy,
                 const float* __restrict__ gconf, float* __restrict__ gout)
{
    extern __shared__ float smem_raw[];
    float2* shSD = reinterpret_cast<float2*>(smem_raw);   // [SH][TW] (S,D)
    float2* shAB = shSD + SH * TW;                        // [SH][TW] (A,B)

    const int tid = threadIdx.x;
    const int col = tid & 63;               // phase-2: one column per thread
    const int ry  = tid >> 6;               // phase-2: row group 0..3
    const int x0  = blockIdx.x * TW;
    const int y0  = blockIdx.y * TH;
    const int zc  = blockIdx.z;             // b*3 + c
    const int b   = zc / 3;
    const int c   = zc - 3 * b;

    const float C1c = 0.0001f;   // 0.01^2
    const float C2c = 0.0009f;   // 0.03^2

    const float* cbase = gconf + (size_t)b * (HH * WW) + (size_t)y0 * WW + (x0 + col);
    const float* xb = gx + (size_t)(b * CH + c) * (HH * WW);
    const float* yb = gy + (size_t)(b * CH + c) * (HH * WW);

    float tsum = 0.0f;           // running sum of loss*conf over my pixels

    // ---- Phase 1: horizontal conv of {s,d,s^2,d^2} from GLOBAL -> smem ----
    // Unit (r,g), g in 0..7: smem row r, output cols 8g..8g+7. Taps span
    // image cols x0+8g-5 .. x0+8g+12, covered by 7 aligned float4s from
    // x0+8g-8. After the (S,D) convs, vs/vd are squared IN PLACE and the
    // same chains produce the (A,B) convs.
    for (int u = tid; u < SH * 8; u += 256) {
        const int r = u >> 3;
        const int g = u & 7;
        const int grow = y0 + r - HALO;
        const bool rok = (unsigned)grow < (unsigned)HH;
        const float4* xrow = reinterpret_cast<const float4*>(xb + (size_t)grow * WW);
        const float4* yrow = reinterpret_cast<const float4*>(yb + (size_t)grow * WW);
        const int c0 = x0 + 8 * g - 8;     // first float4 col (aligned)

        float vs[28], vd[28];
#pragma unroll
        for (int q = 0; q < 7; ++q) {
            const int gc = c0 + 4 * q;
            float4 fx = make_float4(0.f, 0.f, 0.f, 0.f);
            float4 fy = make_float4(0.f, 0.f, 0.f, 0.f);
            if (rok && (unsigned)gc < (unsigned)WW) {
                fx = xrow[gc >> 2];
                fy = yrow[gc >> 2];
            }
            vs[4*q+0] = fx.x + fy.x;  vd[4*q+0] = fx.x - fy.x;
            vs[4*q+1] = fx.y + fy.y;  vd[4*q+1] = fx.y - fy.y;
            vs[4*q+2] = fx.z + fy.z;  vd[4*q+2] = fx.z - fy.z;
            vs[4*q+3] = fx.w + fy.w;  vd[4*q+3] = fx.w - fy.w;
        }

        // conv of s and d -> interleaved (S,D) store. Output j uses vs[j+3..j+13].
#pragma unroll
        for (int j = 0; j < 8; ++j) {
            float hs = vs[j+3] * gw(0);
            float hd = vd[j+3] * gw(0);
#pragma unroll
            for (int k = 1; k < 11; ++k) {
                hs = fmaf(vs[j+3+k], gw(k), hs);
                hd = fmaf(vd[j+3+k], gw(k), hd);
            }
            shSD[r * TW + 8 * g + j] = make_float2(hs, hd);
        }

        // in-place squares (only indices 3..20 feed the (A,B) convs)
#pragma unroll
        for (int i = 3; i < 21; ++i) {
            vs[i] = vs[i] * vs[i];
            vd[i] = vd[i] * vd[i];
        }
#pragma unroll
        for (int j = 0; j < 8; ++j) {
            float hs2 = vs[j+3] * gw(0);
            float hd2 = vd[j+3] * gw(0);
#pragma unroll
            for (int k = 1; k < 11; ++k) {
                hs2 = fmaf(vs[j+3+k], gw(k), hs2);
                hd2 = fmaf(vd[j+3+k], gw(k), hd2);
            }
            shAB[r * TW + 8 * g + j] = make_float2(hs2, hd2);
        }
    }
    __syncthreads();

    // ---- Phase 2: two passes of (8 rows x 1 col), vertical conv + SSIM ----
#pragma unroll
    for (int pass = 0; pass < 2; ++pass) {
        const int rbase = 8 * ry + 32 * pass;

        float t1[8], t3[8];
        {
            const float2* bp = shSD + col;
            float2 v[18];
#pragma unroll
            for (int r = 0; r < 18; ++r) v[r] = bp[(rbase + r) * TW];
#pragma unroll
            for (int j = 0; j < 8; ++j) {
                float aS = v[j].x * gw(0);
                float aD = v[j].y * gw(0);
#pragma unroll
                for (int k = 1; k < 11; ++k) {
                    aS = fmaf(v[j+k].x, gw(k), aS);
                    aD = fmaf(v[j+k].y, gw(k), aD);
                }
                const float P = aS * aS;
                const float Q = aD * aD;
                t1[j] = 0.5f * (P - Q);        // 2*mu_x*mu_y
                t3[j] = 0.5f * (P + Q);        // mu_x^2 + mu_y^2
            }
        }

        {
            const float2* bp = shAB + col;
            float2 v[18];
#pragma unroll
            for (int r = 0; r < 18; ++r) v[r] = bp[(rbase + r) * TW];
#pragma unroll
            for (int j = 0; j < 8; ++j) {
                float aA = v[j].x * gw(0);
                float aB = v[j].y * gw(0);
#pragma unroll
                for (int k = 1; k < 11; ++k) {
                    aA = fmaf(v[j+k].x, gw(k), aA);
                    aB = fmaf(v[j+k].y, gw(k), aB);
                }
                const float t2 = 0.5f * (aA - aB) - t1[j];   // 2*sigma_xy
                const float t4 = 0.5f * (aA + aB) - t3[j];   // sx^2+sy^2
                const float num = (t1[j] + C1c) * (t2 + C2c);
                const float den = (t3[j] + C1c) * (t4 + C2c);
                float loss = 1.0f - __fdividef(num, den);
                loss = fminf(fmaxf(loss, 0.0f), 1.0f);
                tsum += loss * cbase[(size_t)(rbase + j) * WW];
            }
        }
    }

    // ---- block reduction + device-global accumulation + finalize ----
#pragma unroll
    for (int off = 16; off > 0; off >>= 1)
        tsum += __shfl_down_sync(0xffffffffu, tsum, off);

    __shared__ float wsum[8];
    if ((tid & 31) == 0) wsum[tid >> 5] = tsum;
    __syncthreads();
    if (tid == 0) {
        float s = 0.0f;
#pragma unroll
        for (int i = 0; i < 8; ++i) s += wsum[i];
        atomicAdd(&g_accum, s);
        __threadfence();
        const unsigned t = atomicAdd(&g_ticket, 1u);
        if (t == NBLOCKS - 1) {
            const float total = *((volatile float*)&g_accum);
            const float inv_n = 1.0f / (float)(BATCH * CH * HH * WW);
            *gout = total * inv_n;
            g_accum  = 0.0f;      // reset for next graph replay
            g_ticket = 0u;
        }
    }
}

extern "C" void kernel_launch(void* const* d_in, const int* in_sizes, int n_in,
                              void* d_out, int out_size)
{
    const float* x    = (const float*)d_in[0];
    const float* y    = (const float*)d_in[1];
    const float* conf = (const float*)d_in[2];
    float* out = (float*)d_out;

    cudaFuncSetAttribute(ssim_tile_kernel,
                         cudaFuncAttributeMaxDynamicSharedMemorySize, SMEM_BYTES);

    dim3 grid(WW / TW, HH / TH, BATCH * CH);   // 8 x 8 x 48 = 3072 blocks
    ssim_tile_kernel<<<grid, 256, SMEM_BYTES>>>(x, y, conf, out);
}

// round 12
// speedup vs baseline: 1.1410x; 1.1410x over previous
#include <cuda_runtime.h>

// ---------------------------------------------------------------------------
// ConfidenceAwareSSIM: B=16, C=3, H=W=512, fp32.
// loss = mean( clip(1 - SSIM(x,y), 0, 1) * conf ), 11x11 Gaussian, zero pad.
//
// R12 changes vs R9 (74.2us best; R11 8-wide units FAILED: 592 units/256thr
// = 2.31 -> 30% phase-1 imbalance; reverted):
//  * Phase 2: single pass, 16 rows x 1 col per thread (64 cols x 4 groups =
//    exactly 256 threads, perfectly balanced). 26-row window per array via
//    two 11-deep float2 ring buffers -> 52 LDS.64 per 16 pixels instead of
//    72 (-28% phase-2 LDS bytes). Per-j interleave of both conv chains +
//    SSIM improves ILP mix.
// ---------------------------------------------------------------------------

#define BATCH 16
#define CH    3
#define HH    512
#define WW    512

#define TW    64
#define TH    64
#define HALO  5
#define SH    (TH + 2*HALO)       // 74
#define NBLOCKS (8*8*48)

#define SMEM_FLOATS (4*SH*TW)     // two float2 planes: (S,D), (A,B)
#define SMEM_BYTES  (SMEM_FLOATS * 4)   // 75,776 B

// Gaussian taps (symmetric, normalized) as literals.
__device__ __forceinline__ constexpr float gw(int k) {
    const int d = (k <= 5) ? k : (10 - k);
    return (d == 0) ? 0.00102838f
         : (d == 1) ? 0.00759876f
         : (d == 2) ? 0.03600078f
         : (d == 3) ? 0.10936070f
         : (d == 4) ? 0.21300554f
         :            0.26601173f;
}

__device__ float    g_accum  = 0.0f;
__device__ unsigned g_ticket = 0u;

__global__ void __launch_bounds__(256, 3)
ssim_tile_kernel(const float* __restrict__ gx, const float* __restrict__ gy,
                 const float* __restrict__ gconf, float* __restrict__ gout)
{
    extern __shared__ float smem_raw[];
    float2* shSD = reinterpret_cast<float2*>(smem_raw);   // [SH][TW] (S,D)
    float2* shAB = shSD + SH * TW;                        // [SH][TW] (A,B)

    const int tid = threadIdx.x;
    const int col = tid & 63;               // phase-2: one column per thread
    const int ry  = tid >> 6;               // phase-2: row group 0..3 (16 rows)
    const int x0  = blockIdx.x * TW;
    const int y0  = blockIdx.y * TH;
    const int zc  = blockIdx.z;             // b*3 + c
    const int b   = zc / 3;
    const int c   = zc - 3 * b;

    const float C1c = 0.0001f;   // 0.01^2
    const float C2c = 0.0009f;   // 0.03^2

    const float* cbase = gconf + (size_t)b * (HH * WW) + (size_t)y0 * WW + (x0 + col);
    const float* xb = gx + (size_t)(b * CH + c) * (HH * WW);
    const float* yb = gy + (size_t)(b * CH + c) * (HH * WW);

    float tsum = 0.0f;           // running sum of loss*conf over my pixels

    // ---- Phase 1: horizontal conv of {s,d,s^2,d^2} from GLOBAL -> smem ----
    // Unit (r,g): smem row r, output cols 4g..4g+3. Taps span image cols
    // x0+4g-5 .. x0+4g+8, covered by 5 aligned float4s starting x0+4g-8.
    for (int u = tid; u < SH * 16; u += 256) {
        const int r = u >> 4;
        const int g = u & 15;
        const int grow = y0 + r - HALO;
        const bool rok = (unsigned)grow < (unsigned)HH;
        const float4* xrow = reinterpret_cast<const float4*>(xb + (size_t)grow * WW);
        const float4* yrow = reinterpret_cast<const float4*>(yb + (size_t)grow * WW);
        const int c0 = x0 + 4 * g - 8;     // first float4 col (aligned)

        float vs[20], vd[20];
#pragma unroll
        for (int q = 0; q < 5; ++q) {
            const int gc = c0 + 4 * q;
            float4 fx = make_float4(0.f, 0.f, 0.f, 0.f);
            float4 fy = make_float4(0.f, 0.f, 0.f, 0.f);
            if (rok && (unsigned)gc < (unsigned)WW) {
                fx = xrow[gc >> 2];
                fy = yrow[gc >> 2];
            }
            vs[4*q+0] = fx.x + fy.x;  vd[4*q+0] = fx.x - fy.x;
            vs[4*q+1] = fx.y + fy.y;  vd[4*q+1] = fx.y - fy.y;
            vs[4*q+2] = fx.z + fy.z;  vd[4*q+2] = fx.z - fy.z;
            vs[4*q+3] = fx.w + fy.w;  vd[4*q+3] = fx.w - fy.w;
        }

        // conv of s and d -> interleaved (S,D) store
#pragma unroll
        for (int j = 0; j < 4; ++j) {
            float hs = vs[j+3] * gw(0);
            float hd = vd[j+3] * gw(0);
#pragma unroll
            for (int k = 1; k < 11; ++k) {
                hs = fmaf(vs[j+3+k], gw(k), hs);
                hd = fmaf(vd[j+3+k], gw(k), hd);
            }
            shSD[r * TW + 4 * g + j] = make_float2(hs, hd);
        }

        // squares (span indices 3..16 -> s2[0..13]) then their conv
        float s2[14], d2[14];
#pragma unroll
        for (int i = 0; i < 14; ++i) {
            s2[i] = vs[i+3] * vs[i+3];
            d2[i] = vd[i+3] * vd[i+3];
        }
#pragma unroll
        for (int j = 0; j < 4; ++j) {
            float hs2 = s2[j] * gw(0);
            float hd2 = d2[j] * gw(0);
#pragma unroll
            for (int k = 1; k < 11; ++k) {
                hs2 = fmaf(s2[j+k], gw(k), hs2);
                hd2 = fmaf(d2[j+k], gw(k), hd2);
            }
            shAB[r * TW + 4 * g + j] = make_float2(hs2, hd2);
        }
    }
    __syncthreads();

    // ---- Phase 2: single pass, 16 rows x 1 col, dual ring buffers ----
    {
        const int rbase = 16 * ry;
        const float2* bSD = shSD + col;
        const float2* bAB = shAB + col;

        float2 vSD[11], vAB[11];
#pragma unroll
        for (int r = 0; r < 11; ++r) {
            vSD[r] = bSD[(rbase + r) * TW];
            vAB[r] = bAB[(rbase + r) * TW];
        }

#pragma unroll
        for (int j = 0; j < 16; ++j) {
            float aS = vSD[j % 11].x * gw(0);
            float aD = vSD[j % 11].y * gw(0);
            float aA = vAB[j % 11].x * gw(0);
            float aB = vAB[j % 11].y * gw(0);
#pragma unroll
            for (int k = 1; k < 11; ++k) {
                const int i = (j + k) % 11;
                aS = fmaf(vSD[i].x, gw(k), aS);
                aD = fmaf(vSD[i].y, gw(k), aD);
                aA = fmaf(vAB[i].x, gw(k), aA);
                aB = fmaf(vAB[i].y, gw(k), aB);
            }
            if (j < 15) {                       // refill ring slot just freed
                vSD[j % 11] = bSD[(rbase + 11 + j) * TW];
                vAB[j % 11] = bAB[(rbase + 11 + j) * TW];
            }

            const float P = aS * aS;
            const float Q = aD * aD;
            const float t1 = 0.5f * (P - Q);        // 2*mu_x*mu_y
            const float t3 = 0.5f * (P + Q);        // mu_x^2 + mu_y^2
            const float t2 = 0.5f * (aA - aB) - t1; // 2*sigma_xy
            const float t4 = 0.5f * (aA + aB) - t3; // sx^2 + sy^2
            const float num = (t1 + C1c) * (t2 + C2c);
            const float den = (t3 + C1c) * (t4 + C2c);
            float loss = 1.0f - __fdividef(num, den);
            loss = fminf(fmaxf(loss, 0.0f), 1.0f);
            tsum += loss * cbase[(size_t)(rbase + j) * WW];
        }
    }

    // ---- block reduction + device-global accumulation + finalize ----
#pragma unroll
    for (int off = 16; off > 0; off >>= 1)
        tsum += __shfl_down_sync(0xffffffffu, tsum, off);

    __shared__ float wsum[8];
    if ((tid & 31) == 0) wsum[tid >> 5] = tsum;
    __syncthreads();
    if (tid == 0) {
        float s = 0.0f;
#pragma unroll
        for (int i = 0; i < 8; ++i) s += wsum[i];
        atomicAdd(&g_accum, s);
        __threadfence();
        const unsigned t = atomicAdd(&g_ticket, 1u);
        if (t == NBLOCKS - 1) {
            const float total = *((volatile float*)&g_accum);
            const float inv_n = 1.0f / (float)(BATCH * CH * HH * WW);
            *gout = total * inv_n;
            g_accum  = 0.0f;      // reset for next graph replay
            g_ticket = 0u;
        }
    }
}

extern "C" void kernel_launch(void* const* d_in, const int* in_sizes, int n_in,
                              void* d_out, int out_size)
{
    const float* x    = (const float*)d_in[0];
    const float* y    = (const float*)d_in[1];
    const float* conf = (const float*)d_in[2];
    float* out = (float*)d_out;

    cudaFuncSetAttribute(ssim_tile_kernel,
                         cudaFuncAttributeMaxDynamicSharedMemorySize, SMEM_BYTES);

    dim3 grid(WW / TW, HH / TH, BATCH * CH);   // 8 x 8 x 48 = 3072 blocks
    ssim_tile_kernel<<<grid, 256, SMEM_BYTES>>>(x, y, conf, out);
}

// round 13
// speedup vs baseline: 1.1690x; 1.0246x over previous
#include <cuda_runtime.h>

// ---------------------------------------------------------------------------
// ConfidenceAwareSSIM: B=16, C=3, H=W=512, fp32.
// loss = mean( clip(1 - SSIM(x,y), 0, 1) * conf ), 11x11 Gaussian, zero pad.
//
// R13 changes vs R9 (74.2us best; R12 ring-buffer FAILED: serialized LDS,
// reverted to R9's batch-load phase 2):
//  * Phase-1 stores vectorized: 4 j-outputs buffered, written as 2 STS.128
//    per plane (was 4 STS.64). Old pattern was 4-way bank-conflicted
//    (lanes at col 4g+j -> banks {4g+j} mod 16 = 4 values); 128-bit stores
//    are only 2-way conflicted per 8-lane phase -> ~4x fewer STS wavefronts.
//  * #pragma unroll 2 on the phase-1 unit loop: two units' LDG.128 batches
//    in flight (MLP ~20) to hide DRAM/L2 latency at tile start.
// ---------------------------------------------------------------------------

#define BATCH 16
#define CH    3
#define HH    512
#define WW    512

#define TW    64
#define TH    64
#define HALO  5
#define SH    (TH + 2*HALO)       // 74
#define NBLOCKS (8*8*48)

#define SMEM_FLOATS (4*SH*TW)     // two float2 planes: (S,D), (A,B)
#define SMEM_BYTES  (SMEM_FLOATS * 4)   // 75,776 B

// Gaussian taps (symmetric, normalized) as literals.
__device__ __forceinline__ constexpr float gw(int k) {
    const int d = (k <= 5) ? k : (10 - k);
    return (d == 0) ? 0.00102838f
         : (d == 1) ? 0.00759876f
         : (d == 2) ? 0.03600078f
         : (d == 3) ? 0.10936070f
         : (d == 4) ? 0.21300554f
         :            0.26601173f;
}

__device__ float    g_accum  = 0.0f;
__device__ unsigned g_ticket = 0u;

__global__ void __launch_bounds__(256, 3)
ssim_tile_kernel(const float* __restrict__ gx, const float* __restrict__ gy,
                 const float* __restrict__ gconf, float* __restrict__ gout)
{
    extern __shared__ float smem_raw[];
    float2* shSD = reinterpret_cast<float2*>(smem_raw);   // [SH][TW] (S,D)
    float2* shAB = shSD + SH * TW;                        // [SH][TW] (A,B)

    const int tid = threadIdx.x;
    const int col = tid & 63;               // phase-2: one column per thread
    const int ry  = tid >> 6;               // phase-2: row group 0..3
    const int x0  = blockIdx.x * TW;
    const int y0  = blockIdx.y * TH;
    const int zc  = blockIdx.z;             // b*3 + c
    const int b   = zc / 3;
    const int c   = zc - 3 * b;

    const float C1c = 0.0001f;   // 0.01^2
    const float C2c = 0.0009f;   // 0.03^2

    const float* cbase = gconf + (size_t)b * (HH * WW) + (size_t)y0 * WW + (x0 + col);
    const float* xb = gx + (size_t)(b * CH + c) * (HH * WW);
    const float* yb = gy + (size_t)(b * CH + c) * (HH * WW);

    float tsum = 0.0f;           // running sum of loss*conf over my pixels

    // ---- Phase 1: horizontal conv of {s,d,s^2,d^2} from GLOBAL -> smem ----
    // Unit (r,g): smem row r, output cols 4g..4g+3. Taps span image cols
    // x0+4g-5 .. x0+4g+8, covered by 5 aligned float4s starting x0+4g-8.
#pragma unroll 2
    for (int u = tid; u < SH * 16; u += 256) {
        const int r = u >> 4;
        const int g = u & 15;
        const int grow = y0 + r - HALO;
        const bool rok = (unsigned)grow < (unsigned)HH;
        const float4* xrow = reinterpret_cast<const float4*>(xb + (size_t)grow * WW);
        const float4* yrow = reinterpret_cast<const float4*>(yb + (size_t)grow * WW);
        const int c0 = x0 + 4 * g - 8;     // first float4 col (aligned)

        float vs[20], vd[20];
#pragma unroll
        for (int q = 0; q < 5; ++q) {
            const int gc = c0 + 4 * q;
            float4 fx = make_float4(0.f, 0.f, 0.f, 0.f);
            float4 fy = make_float4(0.f, 0.f, 0.f, 0.f);
            if (rok && (unsigned)gc < (unsigned)WW) {
                fx = xrow[gc >> 2];
                fy = yrow[gc >> 2];
            }
            vs[4*q+0] = fx.x + fy.x;  vd[4*q+0] = fx.x - fy.x;
            vs[4*q+1] = fx.y + fy.y;  vd[4*q+1] = fx.y - fy.y;
            vs[4*q+2] = fx.z + fy.z;  vd[4*q+2] = fx.z - fy.z;
            vs[4*q+3] = fx.w + fy.w;  vd[4*q+3] = fx.w - fy.w;
        }

        // conv of s and d -> buffered, then 2 STS.128 (2-way conflicts
        // instead of 4 STS.64 at 4-way)
        {
            float hs[4], hd[4];
#pragma unroll
            for (int j = 0; j < 4; ++j) {
                float a = vs[j+3] * gw(0);
                float bb = vd[j+3] * gw(0);
#pragma unroll
                for (int k = 1; k < 11; ++k) {
                    a  = fmaf(vs[j+3+k], gw(k), a);
                    bb = fmaf(vd[j+3+k], gw(k), bb);
                }
                hs[j] = a; hd[j] = bb;
            }
            float4* p = reinterpret_cast<float4*>(shSD + r * TW + 4 * g);
            p[0] = make_float4(hs[0], hd[0], hs[1], hd[1]);
            p[1] = make_float4(hs[2], hd[2], hs[3], hd[3]);
        }

        // squares (span indices 3..16 -> s2[0..13]) then their conv
        {
            float s2[14], d2[14];
#pragma unroll
            for (int i = 0; i < 14; ++i) {
                s2[i] = vs[i+3] * vs[i+3];
                d2[i] = vd[i+3] * vd[i+3];
            }
            float ha[4], hb[4];
#pragma unroll
            for (int j = 0; j < 4; ++j) {
                float a = s2[j] * gw(0);
                float bb = d2[j] * gw(0);
#pragma unroll
                for (int k = 1; k < 11; ++k) {
                    a  = fmaf(s2[j+k], gw(k), a);
                    bb = fmaf(d2[j+k], gw(k), bb);
                }
                ha[j] = a; hb[j] = bb;
            }
            float4* p = reinterpret_cast<float4*>(shAB + r * TW + 4 * g);
            p[0] = make_float4(ha[0], hb[0], ha[1], hb[1]);
            p[1] = make_float4(ha[2], hb[2], ha[3], hb[3]);
        }
    }
    __syncthreads();

    // ---- Phase 2: two passes of (8 rows x 1 col), vertical conv + SSIM ----
#pragma unroll
    for (int pass = 0; pass < 2; ++pass) {
        const int rbase = 8 * ry + 32 * pass;

        float t1[8], t3[8];
        {
            const float2* bp = shSD + col;
            float2 v[18];
#pragma unroll
            for (int r = 0; r < 18; ++r) v[r] = bp[(rbase + r) * TW];
#pragma unroll
            for (int j = 0; j < 8; ++j) {
                float aS = v[j].x * gw(0);
                float aD = v[j].y * gw(0);
#pragma unroll
                for (int k = 1; k < 11; ++k) {
                    aS = fmaf(v[j+k].x, gw(k), aS);
                    aD = fmaf(v[j+k].y, gw(k), aD);
                }
                const float P = aS * aS;
                const float Q = aD * aD;
                t1[j] = 0.5f * (P - Q);        // 2*mu_x*mu_y
                t3[j] = 0.5f * (P + Q);        // mu_x^2 + mu_y^2
            }
        }

        {
            const float2* bp = shAB + col;
            float2 v[18];
#pragma unroll
            for (int r = 0; r < 18; ++r) v[r] = bp[(rbase + r) * TW];
#pragma unroll
            for (int j = 0; j < 8; ++j) {
                float aA = v[j].x * gw(0);
                float aB = v[j].y * gw(0);
#pragma unroll
                for (int k = 1; k < 11; ++k) {
                    aA = fmaf(v[j+k].x, gw(k), aA);
                    aB = fmaf(v[j+k].y, gw(k), aB);
                }
                const float t2 = 0.5f * (aA - aB) - t1[j];   // 2*sigma_xy
                const float t4 = 0.5f * (aA + aB) - t3[j];   // sx^2+sy^2
                const float num = (t1[j] + C1c) * (t2 + C2c);
                const float den = (t3[j] + C1c) * (t4 + C2c);
                float loss = 1.0f - __fdividef(num, den);
                loss = fminf(fmaxf(loss, 0.0f), 1.0f);
                tsum += loss * cbase[(size_t)(rbase + j) * WW];
            }
        }
    }

    // ---- block reduction + device-global accumulation + finalize ----
#pragma unroll
    for (int off = 16; off > 0; off >>= 1)
        tsum += __shfl_down_sync(0xffffffffu, tsum, off);

    __shared__ float wsum[8];
    if ((tid & 31) == 0) wsum[tid >> 5] = tsum;
    __syncthreads();
    if (tid == 0) {
        float s = 0.0f;
#pragma unroll
        for (int i = 0; i < 8; ++i) s += wsum[i];
        atomicAdd(&g_accum, s);
        __threadfence();
        const unsigned t = atomicAdd(&g_ticket, 1u);
        if (t == NBLOCKS - 1) {
            const float total = *((volatile float*)&g_accum);
            const float inv_n = 1.0f / (float)(BATCH * CH * HH * WW);
            *gout = total * inv_n;
            g_accum  = 0.0f;      // reset for next graph replay
            g_ticket = 0u;
        }
    }
}

extern "C" void kernel_launch(void* const* d_in, const int* in_sizes, int n_in,
                              void* d_out, int out_size)
{
    const float* x    = (const float*)d_in[0];
    const float* y    = (const float*)d_in[1];
    const float* conf = (const float*)d_in[2];
    float* out = (float*)d_out;

    cudaFuncSetAttribute(ssim_tile_kernel,
                         cudaFuncAttributeMaxDynamicSharedMemorySize, SMEM_BYTES);

    dim3 grid(WW / TW, HH / TH, BATCH * CH);   // 8 x 8 x 48 = 3072 blocks
    ssim_tile_kernel<<<grid, 256, SMEM_BYTES>>>(x, y, conf, out);
}